// round 1
// baseline (speedup 1.0000x reference)
#include <cuda_runtime.h>

#define Bc     4
#define Nc     1024
#define Hc     8
#define Dc     64
#define DIMc   512
#define INNERc 512
#define QKV3c  1536
#define BHc    32
#define KKc    716
#define SCALEc 0.125f

// Scratch (device globals: no allocations allowed)
__device__ float g_qkv[Bc * Nc * QKV3c];                       // 25.2 MB  [b*n][3*inner]
__device__ float g_dots[(size_t)BHc * Nc * Nc];                // 128 MB   [bh][i][j]
__device__ float g_att[Bc * Nc * INNERc];                      // 8.4 MB   [b*n][h*d]

// ---------------------------------------------------------------------------
// Kernel 1: qkv = x @ w_qkv     (4096 x 512) @ (512 x 1536)
// 64x64 tile, 256 threads, 4x4 per thread, BK=16
// ---------------------------------------------------------------------------
__global__ __launch_bounds__(256) void k_qkv(const float* __restrict__ x,
                                             const float* __restrict__ w) {
    __shared__ float As[64][17];
    __shared__ float Bs[16][65];
    const int tid = threadIdx.x;
    const int tx = tid & 15, ty = tid >> 4;
    const int row0 = blockIdx.y * 64;
    const int col0 = blockIdx.x * 64;
    float acc[4][4] = {};

    for (int kt = 0; kt < DIMc; kt += 16) {
#pragma unroll
        for (int l = 0; l < 4; l++) {
            int idx = tid + l * 256;
            int r = idx >> 4, c = idx & 15;
            As[r][c] = x[(row0 + r) * DIMc + kt + c];
        }
#pragma unroll
        for (int l = 0; l < 4; l++) {
            int idx = tid + l * 256;
            int r = idx >> 6, c = idx & 63;
            Bs[r][c] = w[(kt + r) * QKV3c + col0 + c];
        }
        __syncthreads();
#pragma unroll
        for (int k = 0; k < 16; k++) {
            float a[4], b[4];
#pragma unroll
            for (int i = 0; i < 4; i++) a[i] = As[ty * 4 + i][k];
#pragma unroll
            for (int j = 0; j < 4; j++) b[j] = Bs[k][tx * 4 + j];
#pragma unroll
            for (int i = 0; i < 4; i++)
#pragma unroll
                for (int j = 0; j < 4; j++)
                    acc[i][j] = fmaf(a[i], b[j], acc[i][j]);
        }
        __syncthreads();
    }
#pragma unroll
    for (int i = 0; i < 4; i++) {
        int r = row0 + ty * 4 + i;
#pragma unroll
        for (int j = 0; j < 4; j++)
            g_qkv[r * QKV3c + col0 + tx * 4 + j] = acc[i][j];
    }
}

// ---------------------------------------------------------------------------
// Kernel 2: dots[bh] = (Q[bh] @ K[bh]^T) * scale    (1024x64)@(64x1024)
// grid (16, 16, 32); block computes 64x64 tile; K-dim = 64 fully in smem
// ---------------------------------------------------------------------------
__global__ __launch_bounds__(256) void k_dots() {
    __shared__ float Qs[64][65];
    __shared__ float Ks[64][65];
    const int tid = threadIdx.x;
    const int tx = tid & 15, ty = tid >> 4;
    const int bh = blockIdx.z;
    const int b = bh >> 3, h = bh & 7;
    const int i0 = blockIdx.y * 64, j0 = blockIdx.x * 64;
    const float* qbase = g_qkv + (size_t)(b * Nc) * QKV3c + h * Dc;
    const float* kbase = g_qkv + (size_t)(b * Nc) * QKV3c + INNERc + h * Dc;

#pragma unroll
    for (int l = 0; l < 16; l++) {
        int idx = tid + l * 256;
        int r = idx >> 6, c = idx & 63;
        Qs[r][c] = qbase[(i0 + r) * QKV3c + c];
        Ks[r][c] = kbase[(j0 + r) * QKV3c + c];
    }
    __syncthreads();

    float acc[4][4] = {};
#pragma unroll 8
    for (int d = 0; d < 64; d++) {
        float a[4], b2[4];
#pragma unroll
        for (int i = 0; i < 4; i++) a[i] = Qs[ty * 4 + i][d];
#pragma unroll
        for (int j = 0; j < 4; j++) b2[j] = Ks[tx * 4 + j][d];
#pragma unroll
        for (int i = 0; i < 4; i++)
#pragma unroll
            for (int j = 0; j < 4; j++)
                acc[i][j] = fmaf(a[i], b2[j], acc[i][j]);
    }

    float* out = g_dots + (size_t)bh * Nc * Nc;
#pragma unroll
    for (int i = 0; i < 4; i++)
#pragma unroll
        for (int j = 0; j < 4; j++)
            out[(size_t)(i0 + ty * 4 + i) * Nc + j0 + tx * 4 + j] = acc[i][j] * SCALEc;
}

// ---------------------------------------------------------------------------
// Kernel 3: exact per-row top-KK threshold + masked softmax (in place)
// One block (256 threads) per row. Ordered-uint radix/linear-bin selection.
// ---------------------------------------------------------------------------
__device__ __forceinline__ unsigned f2o(float x) {
    unsigned u = __float_as_uint(x);
    return (u & 0x80000000u) ? ~u : (u | 0x80000000u);
}
__device__ __forceinline__ float o2f(unsigned u) {
    unsigned f = (u & 0x80000000u) ? (u & 0x7fffffffu) : ~u;
    return __uint_as_float(f);
}

__global__ __launch_bounds__(256) void k_topk() {
    __shared__ int      hist[256];
    __shared__ int      wsum[8];
    __shared__ unsigned wmax[8], wmin[8];
    __shared__ float    wredf[8];
    __shared__ unsigned candU[64];
    __shared__ int      s_bkt, s_r2, s_cnt, s_gc;
    __shared__ unsigned s_thr;

    const int tid = threadIdx.x;
    const int lane = tid & 31, wid = tid >> 5;
    float* base = g_dots + (size_t)blockIdx.x * Nc;

    float4 v4 = reinterpret_cast<float4*>(base)[tid];
    float v[4] = {v4.x, v4.y, v4.z, v4.w};
    unsigned u[4];
#pragma unroll
    for (int l = 0; l < 4; l++) u[l] = f2o(v[l]);

    // block min/max over ordered keys
    unsigned umx = u[0], umn = u[0];
#pragma unroll
    for (int l = 1; l < 4; l++) { umx = max(umx, u[l]); umn = min(umn, u[l]); }
#pragma unroll
    for (int o = 16; o; o >>= 1) {
        umx = max(umx, __shfl_xor_sync(0xffffffffu, umx, o));
        umn = min(umn, __shfl_xor_sync(0xffffffffu, umn, o));
    }
    if (lane == 0) { wmax[wid] = umx; wmin[wid] = umn; }
    __syncthreads();
    umx = wmax[0]; umn = wmin[0];
#pragma unroll
    for (int i = 1; i < 8; i++) { umx = max(umx, wmax[i]); umn = min(umn, wmin[i]); }

    // --- exact selection of ascending rank r = N-KK (0-based) ---
    unsigned long long lo = umn;
    unsigned long long range = (unsigned long long)umx - (unsigned long long)umn + 1ull;
    int r = Nc - KKc;            // 308
    unsigned thr_u = umn;
    bool found = false;

    for (int pass = 0; pass < 8 && !found; pass++) {
        if (range == 1ull) { thr_u = (unsigned)lo; break; }  // uniform across block
        hist[tid] = 0;
        __syncthreads();
        unsigned lo32 = (unsigned)lo;
        unsigned hi32 = (unsigned)(lo + range - 1ull);
#pragma unroll
        for (int l = 0; l < 4; l++) {
            if (u[l] >= lo32 && u[l] <= hi32) {
                int bin = (int)(((unsigned long long)(u[l] - lo32) * 256ull) / range);
                atomicAdd(&hist[bin], 1);
            }
        }
        __syncthreads();
        int myh = hist[tid];
        int h = myh;
#pragma unroll
        for (int o = 1; o < 32; o <<= 1) {
            int t2 = __shfl_up_sync(0xffffffffu, h, o);
            if (lane >= o) h += t2;
        }
        if (lane == 31) wsum[wid] = h;
        __syncthreads();
        int add = 0;
        for (int w2 = 0; w2 < wid; w2++) add += wsum[w2];
        int cum = h + add;  // inclusive cumulative over bins <= tid
        if (cum > r && (cum - myh) <= r) {
            s_bkt = tid; s_r2 = r - (cum - myh); s_cnt = myh;
        }
        __syncthreads();
        int bkt = s_bkt, cnt = s_cnt, r2 = s_r2;
        unsigned long long nlo = lo + ((unsigned long long)bkt * range + 255ull) / 256ull;
        unsigned long long nhi = lo + ((unsigned long long)(bkt + 1) * range + 255ull) / 256ull - 1ull;

        if (cnt <= 64) {
            if (tid == 0) s_gc = 0;
            __syncthreads();
            unsigned glo = (unsigned)nlo, ghi = (unsigned)nhi;
#pragma unroll
            for (int l = 0; l < 4; l++) {
                if (u[l] >= glo && u[l] <= ghi) {
                    int p = atomicAdd(&s_gc, 1);
                    candU[p] = u[l];
                }
            }
            __syncthreads();
            if (tid < cnt) {
                unsigned tu = candU[tid];
                int rk = 0;
                for (int j = 0; j < cnt; j++) {
                    unsigned o2 = candU[j];
                    rk += (o2 < tu) || (o2 == tu && j < tid);
                }
                if (rk == r2) s_thr = tu;
            }
            __syncthreads();
            thr_u = s_thr;
            found = true;
        } else {
            lo = nlo;
            range = nhi - nlo + 1ull;
            r = r2;
            __syncthreads();
        }
    }

    // --- masked softmax: include u >= thr_u ---
    float vmx = o2f(umx);
    float e[4];
    float ls = 0.f;
#pragma unroll
    for (int l = 0; l < 4; l++) {
        e[l] = (u[l] >= thr_u) ? __expf(v[l] - vmx) : 0.f;
        ls += e[l];
    }
#pragma unroll
    for (int o = 16; o; o >>= 1) ls += __shfl_xor_sync(0xffffffffu, ls, o);
    if (lane == 0) wredf[wid] = ls;
    __syncthreads();
    float tot = 0.f;
#pragma unroll
    for (int i = 0; i < 8; i++) tot += wredf[i];
    float inv = 1.0f / tot;
    float4 o4 = make_float4(e[0] * inv, e[1] * inv, e[2] * inv, e[3] * inv);
    reinterpret_cast<float4*>(base)[tid] = o4;
}

// ---------------------------------------------------------------------------
// Kernel 4: att_out[bh] = P[bh] @ V[bh]     (1024x1024)@(1024x64)
// grid (16, 32); block computes 64(rows) x 64(full D) tile; BK=16
// ---------------------------------------------------------------------------
__global__ __launch_bounds__(256) void k_av() {
    __shared__ float Ps[64][17];
    __shared__ float Vs[16][65];
    const int tid = threadIdx.x;
    const int tx = tid & 15, ty = tid >> 4;
    const int bh = blockIdx.y;
    const int b = bh >> 3, h = bh & 7;
    const int i0 = blockIdx.x * 64;
    const float* P = g_dots + (size_t)bh * Nc * Nc;
    const float* vbase = g_qkv + (size_t)(b * Nc) * QKV3c + 2 * INNERc + h * Dc;

    float acc[4][4] = {};
    for (int kt = 0; kt < Nc; kt += 16) {
#pragma unroll
        for (int l = 0; l < 4; l++) {
            int idx = tid + l * 256;
            int r = idx >> 4, c = idx & 15;
            Ps[r][c] = P[(size_t)(i0 + r) * Nc + kt + c];
        }
#pragma unroll
        for (int l = 0; l < 4; l++) {
            int idx = tid + l * 256;
            int r = idx >> 6, c = idx & 63;
            Vs[r][c] = vbase[(kt + r) * QKV3c + c];
        }
        __syncthreads();
#pragma unroll
        for (int k = 0; k < 16; k++) {
            float a[4], b2[4];
#pragma unroll
            for (int i = 0; i < 4; i++) a[i] = Ps[ty * 4 + i][k];
#pragma unroll
            for (int j = 0; j < 4; j++) b2[j] = Vs[k][tx * 4 + j];
#pragma unroll
            for (int i = 0; i < 4; i++)
#pragma unroll
                for (int j = 0; j < 4; j++)
                    acc[i][j] = fmaf(a[i], b2[j], acc[i][j]);
        }
        __syncthreads();
    }
#pragma unroll
    for (int i = 0; i < 4; i++) {
        int rr = b * Nc + i0 + ty * 4 + i;
#pragma unroll
        for (int j = 0; j < 4; j++)
            g_att[rr * INNERc + h * Dc + tx * 4 + j] = acc[i][j];
    }
}

// ---------------------------------------------------------------------------
// Kernel 5: out = att @ w_out + b_out     (4096x512)@(512x512)
// ---------------------------------------------------------------------------
__global__ __launch_bounds__(256) void k_out(const float* __restrict__ w,
                                             const float* __restrict__ bias,
                                             float* __restrict__ out) {
    __shared__ float As[64][17];
    __shared__ float Bs[16][65];
    const int tid = threadIdx.x;
    const int tx = tid & 15, ty = tid >> 4;
    const int row0 = blockIdx.y * 64;
    const int col0 = blockIdx.x * 64;
    float acc[4][4] = {};

    for (int kt = 0; kt < INNERc; kt += 16) {
#pragma unroll
        for (int l = 0; l < 4; l++) {
            int idx = tid + l * 256;
            int r = idx >> 4, c = idx & 15;
            As[r][c] = g_att[(row0 + r) * INNERc + kt + c];
        }
#pragma unroll
        for (int l = 0; l < 4; l++) {
            int idx = tid + l * 256;
            int r = idx >> 6, c = idx & 63;
            Bs[r][c] = w[(kt + r) * DIMc + col0 + c];
        }
        __syncthreads();
#pragma unroll
        for (int k = 0; k < 16; k++) {
            float a[4], b2[4];
#pragma unroll
            for (int i = 0; i < 4; i++) a[i] = As[ty * 4 + i][k];
#pragma unroll
            for (int j = 0; j < 4; j++) b2[j] = Bs[k][tx * 4 + j];
#pragma unroll
            for (int i = 0; i < 4; i++)
#pragma unroll
                for (int j = 0; j < 4; j++)
                    acc[i][j] = fmaf(a[i], b2[j], acc[i][j]);
        }
        __syncthreads();
    }
#pragma unroll
    for (int i = 0; i < 4; i++) {
        int r = row0 + ty * 4 + i;
#pragma unroll
        for (int j = 0; j < 4; j++) {
            int c = col0 + tx * 4 + j;
            out[r * DIMc + c] = acc[i][j] + bias[c];
        }
    }
}

// ---------------------------------------------------------------------------
extern "C" void kernel_launch(void* const* d_in, const int* in_sizes, int n_in,
                              void* d_out, int out_size) {
    const float* x     = (const float*)d_in[0];  // [4,1024,512]
    const float* w_qkv = (const float*)d_in[1];  // [512,1536]
    const float* w_out = (const float*)d_in[2];  // [512,512]
    const float* b_out = (const float*)d_in[3];  // [512]
    float* out = (float*)d_out;                  // [4,1024,512]

    k_qkv<<<dim3(QKV3c / 64, (Bc * Nc) / 64), 256>>>(x, w_qkv);
    k_dots<<<dim3(Nc / 64, Nc / 64, BHc), 256>>>();
    k_topk<<<BHc * Nc, 256>>>();
    k_av<<<dim3(Nc / 64, BHc), 256>>>();
    k_out<<<dim3(DIMc / 64, (Bc * Nc) / 64), 256>>>(w_out, b_out, out);
}

// round 2
// speedup vs baseline: 1.3705x; 1.3705x over previous
#include <cuda_runtime.h>

#define Bc     4
#define Nc     1024
#define Hc     8
#define Dc     64
#define DIMc   512
#define INNERc 512
#define QKV3c  1536
#define BHc    32
#define KKc    716
#define SCALEc 0.125f

// Scratch (device globals: no allocations allowed)
__device__ float g_qkv[Bc * Nc * QKV3c];          // [b*n][3*inner]
__device__ float g_dots[(size_t)BHc * Nc * Nc];   // [bh][i][j]
__device__ float g_att[Bc * Nc * INNERc];         // [b*n][h*d]

// ---------------------------------------------------------------------------
// tf32 helpers
// ---------------------------------------------------------------------------
__device__ __forceinline__ unsigned f2tf(float f) {
    unsigned r;
    asm("cvt.rna.tf32.f32 %0, %1;" : "=r"(r) : "f"(f));
    return r;
}
__device__ __forceinline__ void split_tf32(float v, float& hi, float& lo) {
    unsigned h = f2tf(v);
    float hf = __uint_as_float(h);
    hi = hf;
    lo = __uint_as_float(f2tf(v - hf));
}
__device__ __forceinline__ void mma8(float* c, const float* a, const float* b) {
    asm volatile(
        "mma.sync.aligned.m16n8k8.row.col.f32.tf32.tf32.f32 "
        "{%0,%1,%2,%3}, {%4,%5,%6,%7}, {%8,%9}, {%0,%1,%2,%3};"
        : "+f"(c[0]), "+f"(c[1]), "+f"(c[2]), "+f"(c[3])
        : "r"(__float_as_uint(a[0])), "r"(__float_as_uint(a[1])),
          "r"(__float_as_uint(a[2])), "r"(__float_as_uint(a[3])),
          "r"(__float_as_uint(b[0])), "r"(__float_as_uint(b[1])));
}

// A-fragment load from smem tile S[k][m+pad] (hi part at Sh, lo at Sl)
#define LOAD_AFRAG(ah, al, Sh, Sl, kk, m)                                  \
    do {                                                                   \
        ah[0] = Sh[(kk) + tig][(m)];      al[0] = Sl[(kk) + tig][(m)];     \
        ah[1] = Sh[(kk) + tig][(m) + 8];  al[1] = Sl[(kk) + tig][(m) + 8]; \
        ah[2] = Sh[(kk) + 4 + tig][(m)];  al[2] = Sl[(kk) + 4 + tig][(m)]; \
        ah[3] = Sh[(kk) + 4 + tig][(m) + 8];                               \
        al[3] = Sl[(kk) + 4 + tig][(m) + 8];                               \
    } while (0)

// ---------------------------------------------------------------------------
// Kernel 1: qkv = x @ w_qkv   (4096 x 512) @ (512 x 1536), 3xTF32
// block 128x128, BK=16, 8 warps (4m x 2n), warp tile 32x64
// ---------------------------------------------------------------------------
__global__ __launch_bounds__(256) void k_qkv(const float* __restrict__ x,
                                             const float* __restrict__ w) {
    __shared__ float Ah[16][136], Al[16][136], Bh[16][136], Bl[16][136];
    const int tid = threadIdx.x, lane = tid & 31, wrp = tid >> 5;
    const int wm = wrp >> 1, wn = wrp & 1;
    const int tig = lane & 3, grp = lane >> 2;
    const int row0 = blockIdx.y * 128, col0 = blockIdx.x * 128;
    float acc[2][8][4] = {};

    for (int kt = 0; kt < DIMc; kt += 16) {
        // A tile 128x16 (transpose-store, split)
#pragma unroll
        for (int l = 0; l < 2; l++) {
            int idx = tid + l * 256;
            int m = idx >> 2, c4 = idx & 3;
            float4 v = *(const float4*)&x[(row0 + m) * DIMc + kt + c4 * 4];
            float vv[4] = {v.x, v.y, v.z, v.w};
#pragma unroll
            for (int i = 0; i < 4; i++)
                split_tf32(vv[i], Ah[c4 * 4 + i][m], Al[c4 * 4 + i][m]);
        }
        // B tile 16x128 (direct, split)
#pragma unroll
        for (int l = 0; l < 2; l++) {
            int idx = tid + l * 256;
            int kr = idx >> 5, n4 = idx & 31;
            float4 v = *(const float4*)&w[(kt + kr) * QKV3c + col0 + n4 * 4];
            float vv[4] = {v.x, v.y, v.z, v.w};
#pragma unroll
            for (int i = 0; i < 4; i++)
                split_tf32(vv[i], Bh[kr][n4 * 4 + i], Bl[kr][n4 * 4 + i]);
        }
        __syncthreads();
#pragma unroll
        for (int kk = 0; kk < 16; kk += 8) {
            float ah[2][4], al[2][4];
#pragma unroll
            for (int f = 0; f < 2; f++) {
                int m = wm * 32 + f * 16 + grp;
                LOAD_AFRAG(ah[f], al[f], Ah, Al, kk, m);
            }
#pragma unroll
            for (int g = 0; g < 8; g++) {
                int n = wn * 64 + g * 8 + grp;
                float bh[2], bl[2];
                bh[0] = Bh[kk + tig][n]; bh[1] = Bh[kk + 4 + tig][n];
                bl[0] = Bl[kk + tig][n]; bl[1] = Bl[kk + 4 + tig][n];
#pragma unroll
                for (int f = 0; f < 2; f++) {
                    mma8(acc[f][g], ah[f], bh);
                    mma8(acc[f][g], ah[f], bl);
                    mma8(acc[f][g], al[f], bh);
                }
            }
        }
        __syncthreads();
    }
#pragma unroll
    for (int f = 0; f < 2; f++) {
        int row = row0 + wm * 32 + f * 16 + grp;
#pragma unroll
        for (int g = 0; g < 8; g++) {
            int col = col0 + wn * 64 + g * 8 + tig * 2;
            *(float2*)&g_qkv[row * QKV3c + col] = make_float2(acc[f][g][0], acc[f][g][1]);
            *(float2*)&g_qkv[(row + 8) * QKV3c + col] = make_float2(acc[f][g][2], acc[f][g][3]);
        }
    }
}

// ---------------------------------------------------------------------------
// Kernel 2: dots[bh] = (Q[bh] @ K[bh]^T) * scale, 3xTF32
// block 128x128, K=64 in 4 BK=16 iters
// ---------------------------------------------------------------------------
__global__ __launch_bounds__(256) void k_dots() {
    __shared__ float Ah[16][136], Al[16][136], Bh[16][136], Bl[16][136];
    const int tid = threadIdx.x, lane = tid & 31, wrp = tid >> 5;
    const int wm = wrp >> 1, wn = wrp & 1;
    const int tig = lane & 3, grp = lane >> 2;
    const int bh = blockIdx.z, b = bh >> 3, h = bh & 7;
    const int i0 = blockIdx.y * 128, j0 = blockIdx.x * 128;
    const float* qbase = g_qkv + (size_t)(b * Nc) * QKV3c + h * Dc;
    const float* kbase = g_qkv + (size_t)(b * Nc) * QKV3c + INNERc + h * Dc;
    float acc[2][8][4] = {};

    for (int kt = 0; kt < Dc; kt += 16) {
#pragma unroll
        for (int l = 0; l < 2; l++) {
            int idx = tid + l * 256;
            int m = idx >> 2, c4 = idx & 3;
            float4 v = *(const float4*)&qbase[(i0 + m) * QKV3c + kt + c4 * 4];
            float vv[4] = {v.x, v.y, v.z, v.w};
#pragma unroll
            for (int i = 0; i < 4; i++)
                split_tf32(vv[i], Ah[c4 * 4 + i][m], Al[c4 * 4 + i][m]);
        }
#pragma unroll
        for (int l = 0; l < 2; l++) {
            int idx = tid + l * 256;
            int m = idx >> 2, c4 = idx & 3;
            float4 v = *(const float4*)&kbase[(j0 + m) * QKV3c + kt + c4 * 4];
            float vv[4] = {v.x, v.y, v.z, v.w};
#pragma unroll
            for (int i = 0; i < 4; i++)
                split_tf32(vv[i], Bh[c4 * 4 + i][m], Bl[c4 * 4 + i][m]);
        }
        __syncthreads();
#pragma unroll
        for (int kk = 0; kk < 16; kk += 8) {
            float ah[2][4], al[2][4];
#pragma unroll
            for (int f = 0; f < 2; f++) {
                int m = wm * 32 + f * 16 + grp;
                LOAD_AFRAG(ah[f], al[f], Ah, Al, kk, m);
            }
#pragma unroll
            for (int g = 0; g < 8; g++) {
                int n = wn * 64 + g * 8 + grp;
                float bh2[2], bl2[2];
                bh2[0] = Bh[kk + tig][n]; bh2[1] = Bh[kk + 4 + tig][n];
                bl2[0] = Bl[kk + tig][n]; bl2[1] = Bl[kk + 4 + tig][n];
#pragma unroll
                for (int f = 0; f < 2; f++) {
                    mma8(acc[f][g], ah[f], bh2);
                    mma8(acc[f][g], ah[f], bl2);
                    mma8(acc[f][g], al[f], bh2);
                }
            }
        }
        __syncthreads();
    }
    float* out = g_dots + (size_t)bh * Nc * Nc;
#pragma unroll
    for (int f = 0; f < 2; f++) {
        int row = i0 + wm * 32 + f * 16 + grp;
#pragma unroll
        for (int g = 0; g < 8; g++) {
            int col = j0 + wn * 64 + g * 8 + tig * 2;
            *(float2*)&out[(size_t)row * Nc + col] =
                make_float2(acc[f][g][0] * SCALEc, acc[f][g][1] * SCALEc);
            *(float2*)&out[(size_t)(row + 8) * Nc + col] =
                make_float2(acc[f][g][2] * SCALEc, acc[f][g][3] * SCALEc);
        }
    }
}

// ---------------------------------------------------------------------------
// Kernel 3: exact per-row top-KK threshold + masked softmax (in place)
// ---------------------------------------------------------------------------
__device__ __forceinline__ unsigned f2o(float x) {
    unsigned u = __float_as_uint(x);
    return (u & 0x80000000u) ? ~u : (u | 0x80000000u);
}
__device__ __forceinline__ float o2f(unsigned u) {
    unsigned f = (u & 0x80000000u) ? (u & 0x7fffffffu) : ~u;
    return __uint_as_float(f);
}

__global__ __launch_bounds__(256) void k_topk() {
    __shared__ int      hist[256];
    __shared__ int      wsum[8];
    __shared__ unsigned wmax[8], wmin[8];
    __shared__ float    wredf[8];
    __shared__ unsigned candU[64];
    __shared__ int      s_bkt, s_r2, s_cnt, s_gc;
    __shared__ unsigned s_thr;

    const int tid = threadIdx.x;
    const int lane = tid & 31, wid = tid >> 5;
    float* base = g_dots + (size_t)blockIdx.x * Nc;

    float4 v4 = reinterpret_cast<float4*>(base)[tid];
    float v[4] = {v4.x, v4.y, v4.z, v4.w};
    unsigned u[4];
#pragma unroll
    for (int l = 0; l < 4; l++) u[l] = f2o(v[l]);

    unsigned umx = u[0], umn = u[0];
#pragma unroll
    for (int l = 1; l < 4; l++) { umx = max(umx, u[l]); umn = min(umn, u[l]); }
#pragma unroll
    for (int o = 16; o; o >>= 1) {
        umx = max(umx, __shfl_xor_sync(0xffffffffu, umx, o));
        umn = min(umn, __shfl_xor_sync(0xffffffffu, umn, o));
    }
    if (lane == 0) { wmax[wid] = umx; wmin[wid] = umn; }
    __syncthreads();
    umx = wmax[0]; umn = wmin[0];
#pragma unroll
    for (int i = 1; i < 8; i++) { umx = max(umx, wmax[i]); umn = min(umn, wmin[i]); }

    unsigned long long lo = umn;
    unsigned long long range = (unsigned long long)umx - (unsigned long long)umn + 1ull;
    int r = Nc - KKc;
    unsigned thr_u = umn;
    bool found = false;

    for (int pass = 0; pass < 8 && !found; pass++) {
        if (range == 1ull) { thr_u = (unsigned)lo; break; }
        hist[tid] = 0;
        __syncthreads();
        unsigned lo32 = (unsigned)lo;
        unsigned hi32 = (unsigned)(lo + range - 1ull);
#pragma unroll
        for (int l = 0; l < 4; l++) {
            if (u[l] >= lo32 && u[l] <= hi32) {
                int bin = (int)(((unsigned long long)(u[l] - lo32) * 256ull) / range);
                atomicAdd(&hist[bin], 1);
            }
        }
        __syncthreads();
        int myh = hist[tid];
        int hh = myh;
#pragma unroll
        for (int o = 1; o < 32; o <<= 1) {
            int t2 = __shfl_up_sync(0xffffffffu, hh, o);
            if (lane >= o) hh += t2;
        }
        if (lane == 31) wsum[wid] = hh;
        __syncthreads();
        int add = 0;
        for (int w2 = 0; w2 < wid; w2++) add += wsum[w2];
        int cum = hh + add;
        if (cum > r && (cum - myh) <= r) {
            s_bkt = tid; s_r2 = r - (cum - myh); s_cnt = myh;
        }
        __syncthreads();
        int bkt = s_bkt, cnt = s_cnt, r2 = s_r2;
        unsigned long long nlo = lo + ((unsigned long long)bkt * range + 255ull) / 256ull;
        unsigned long long nhi = lo + ((unsigned long long)(bkt + 1) * range + 255ull) / 256ull - 1ull;

        if (cnt <= 64) {
            if (tid == 0) s_gc = 0;
            __syncthreads();
            unsigned glo = (unsigned)nlo, ghi = (unsigned)nhi;
#pragma unroll
            for (int l = 0; l < 4; l++) {
                if (u[l] >= glo && u[l] <= ghi) {
                    int p = atomicAdd(&s_gc, 1);
                    candU[p] = u[l];
                }
            }
            __syncthreads();
            if (tid < cnt) {
                unsigned tu = candU[tid];
                int rk = 0;
                for (int j = 0; j < cnt; j++) {
                    unsigned o2 = candU[j];
                    rk += (o2 < tu) || (o2 == tu && j < tid);
                }
                if (rk == r2) s_thr = tu;
            }
            __syncthreads();
            thr_u = s_thr;
            found = true;
        } else {
            lo = nlo;
            range = nhi - nlo + 1ull;
            r = r2;
            __syncthreads();
        }
    }

    float vmx = o2f(umx);
    float e[4];
    float ls = 0.f;
#pragma unroll
    for (int l = 0; l < 4; l++) {
        e[l] = (u[l] >= thr_u) ? __expf(v[l] - vmx) : 0.f;
        ls += e[l];
    }
#pragma unroll
    for (int o = 16; o; o >>= 1) ls += __shfl_xor_sync(0xffffffffu, ls, o);
    if (lane == 0) wredf[wid] = ls;
    __syncthreads();
    float tot = 0.f;
#pragma unroll
    for (int i = 0; i < 8; i++) tot += wredf[i];
    float inv = 1.0f / tot;
    float4 o4 = make_float4(e[0] * inv, e[1] * inv, e[2] * inv, e[3] * inv);
    reinterpret_cast<float4*>(base)[tid] = o4;
}

// ---------------------------------------------------------------------------
// Kernel 4: att[bh] = P[bh] @ V[bh]   (1024x1024)@(1024x64), 3xTF32
// block 128(m) x 64(n), BK=16, warp tile 32x32
// ---------------------------------------------------------------------------
__global__ __launch_bounds__(256) void k_av() {
    __shared__ float Ah[16][136], Al[16][136], Bh[16][72], Bl[16][72];
    const int tid = threadIdx.x, lane = tid & 31, wrp = tid >> 5;
    const int wm = wrp >> 1, wn = wrp & 1;
    const int tig = lane & 3, grp = lane >> 2;
    const int bh = blockIdx.y, b = bh >> 3, h = bh & 7;
    const int i0 = blockIdx.x * 128;
    const float* P = g_dots + (size_t)bh * Nc * Nc;
    const float* vbase = g_qkv + (size_t)(b * Nc) * QKV3c + 2 * INNERc + h * Dc;
    float acc[2][4][4] = {};

    for (int kt = 0; kt < Nc; kt += 16) {
        // A = P tile 128x16 (transpose, split)
#pragma unroll
        for (int l = 0; l < 2; l++) {
            int idx = tid + l * 256;
            int m = idx >> 2, c4 = idx & 3;
            float4 v = *(const float4*)&P[(size_t)(i0 + m) * Nc + kt + c4 * 4];
            float vv[4] = {v.x, v.y, v.z, v.w};
#pragma unroll
            for (int i = 0; i < 4; i++)
                split_tf32(vv[i], Ah[c4 * 4 + i][m], Al[c4 * 4 + i][m]);
        }
        // B = V tile 16x64 (direct, split)
        {
            int kr = tid >> 4, n4 = tid & 15;
            float4 v = *(const float4*)&vbase[(kt + kr) * QKV3c + n4 * 4];
            float vv[4] = {v.x, v.y, v.z, v.w};
#pragma unroll
            for (int i = 0; i < 4; i++)
                split_tf32(vv[i], Bh[kr][n4 * 4 + i], Bl[kr][n4 * 4 + i]);
        }
        __syncthreads();
#pragma unroll
        for (int kk = 0; kk < 16; kk += 8) {
            float ah[2][4], al[2][4];
#pragma unroll
            for (int f = 0; f < 2; f++) {
                int m = wm * 32 + f * 16 + grp;
                LOAD_AFRAG(ah[f], al[f], Ah, Al, kk, m);
            }
#pragma unroll
            for (int g = 0; g < 4; g++) {
                int n = wn * 32 + g * 8 + grp;
                float bh2[2], bl2[2];
                bh2[0] = Bh[kk + tig][n]; bh2[1] = Bh[kk + 4 + tig][n];
                bl2[0] = Bl[kk + tig][n]; bl2[1] = Bl[kk + 4 + tig][n];
#pragma unroll
                for (int f = 0; f < 2; f++) {
                    mma8(acc[f][g], ah[f], bh2);
                    mma8(acc[f][g], ah[f], bl2);
                    mma8(acc[f][g], al[f], bh2);
                }
            }
        }
        __syncthreads();
    }
#pragma unroll
    for (int f = 0; f < 2; f++) {
        int rr = b * Nc + i0 + wm * 32 + f * 16 + grp;
#pragma unroll
        for (int g = 0; g < 4; g++) {
            int col = h * Dc + wn * 32 + g * 8 + tig * 2;
            *(float2*)&g_att[rr * INNERc + col] = make_float2(acc[f][g][0], acc[f][g][1]);
            *(float2*)&g_att[(rr + 8) * INNERc + col] = make_float2(acc[f][g][2], acc[f][g][3]);
        }
    }
}

// ---------------------------------------------------------------------------
// Kernel 5: out = att @ w_out + b_out   (4096x512)@(512x512), 3xTF32
// ---------------------------------------------------------------------------
__global__ __launch_bounds__(256) void k_out(const float* __restrict__ w,
                                             const float* __restrict__ bias,
                                             float* __restrict__ out) {
    __shared__ float Ah[16][136], Al[16][136], Bh[16][136], Bl[16][136];
    const int tid = threadIdx.x, lane = tid & 31, wrp = tid >> 5;
    const int wm = wrp >> 1, wn = wrp & 1;
    const int tig = lane & 3, grp = lane >> 2;
    const int row0 = blockIdx.y * 128, col0 = blockIdx.x * 128;
    float acc[2][8][4] = {};

    for (int kt = 0; kt < INNERc; kt += 16) {
#pragma unroll
        for (int l = 0; l < 2; l++) {
            int idx = tid + l * 256;
            int m = idx >> 2, c4 = idx & 3;
            float4 v = *(const float4*)&g_att[(row0 + m) * INNERc + kt + c4 * 4];
            float vv[4] = {v.x, v.y, v.z, v.w};
#pragma unroll
            for (int i = 0; i < 4; i++)
                split_tf32(vv[i], Ah[c4 * 4 + i][m], Al[c4 * 4 + i][m]);
        }
#pragma unroll
        for (int l = 0; l < 2; l++) {
            int idx = tid + l * 256;
            int kr = idx >> 5, n4 = idx & 31;
            float4 v = *(const float4*)&w[(kt + kr) * DIMc + col0 + n4 * 4];
            float vv[4] = {v.x, v.y, v.z, v.w};
#pragma unroll
            for (int i = 0; i < 4; i++)
                split_tf32(vv[i], Bh[kr][n4 * 4 + i], Bl[kr][n4 * 4 + i]);
        }
        __syncthreads();
#pragma unroll
        for (int kk = 0; kk < 16; kk += 8) {
            float ah[2][4], al[2][4];
#pragma unroll
            for (int f = 0; f < 2; f++) {
                int m = wm * 32 + f * 16 + grp;
                LOAD_AFRAG(ah[f], al[f], Ah, Al, kk, m);
            }
#pragma unroll
            for (int g = 0; g < 8; g++) {
                int n = wn * 64 + g * 8 + grp;
                float bh2[2], bl2[2];
                bh2[0] = Bh[kk + tig][n]; bh2[1] = Bh[kk + 4 + tig][n];
                bl2[0] = Bl[kk + tig][n]; bl2[1] = Bl[kk + 4 + tig][n];
#pragma unroll
                for (int f = 0; f < 2; f++) {
                    mma8(acc[f][g], ah[f], bh2);
                    mma8(acc[f][g], ah[f], bl2);
                    mma8(acc[f][g], al[f], bh2);
                }
            }
        }
        __syncthreads();
    }
#pragma unroll
    for (int f = 0; f < 2; f++) {
        int row = row0 + wm * 32 + f * 16 + grp;
#pragma unroll
        for (int g = 0; g < 8; g++) {
            int col = col0 + wn * 64 + g * 8 + tig * 2;
            float b0 = bias[col], b1 = bias[col + 1];
            *(float2*)&out[row * DIMc + col] =
                make_float2(acc[f][g][0] + b0, acc[f][g][1] + b1);
            *(float2*)&out[(row + 8) * DIMc + col] =
                make_float2(acc[f][g][2] + b0, acc[f][g][3] + b1);
        }
    }
}

// ---------------------------------------------------------------------------
extern "C" void kernel_launch(void* const* d_in, const int* in_sizes, int n_in,
                              void* d_out, int out_size) {
    const float* x     = (const float*)d_in[0];  // [4,1024,512]
    const float* w_qkv = (const float*)d_in[1];  // [512,1536]
    const float* w_out = (const float*)d_in[2];  // [512,512]
    const float* b_out = (const float*)d_in[3];  // [512]
    float* out = (float*)d_out;                  // [4,1024,512]

    k_qkv<<<dim3(QKV3c / 128, (Bc * Nc) / 128), 256>>>(x, w_qkv);
    k_dots<<<dim3(Nc / 128, Nc / 128, BHc), 256>>>();
    k_topk<<<BHc * Nc, 256>>>();
    k_av<<<dim3(Nc / 128, BHc), 256>>>();
    k_out<<<dim3(DIMc / 128, (Bc * Nc) / 128), 256>>>(w_out, b_out, out);
}